// round 8
// baseline (speedup 1.0000x reference)
#include <cuda_runtime.h>

#define ADAM_B1 0.9f
#define ADAM_B2 0.999f
#define ADAM_LR 0.02f

// ---------------- packed f32x2 helpers ----------------
struct F2 { unsigned long long v; };

__device__ __forceinline__ F2 pk(float lo, float hi) {
    F2 r; asm("mov.b64 %0, {%1, %2};" : "=l"(r.v) : "f"(lo), "f"(hi)); return r;
}
__device__ __forceinline__ void upk(F2 a, float& lo, float& hi) {
    asm("mov.b64 {%0, %1}, %2;" : "=f"(lo), "=f"(hi) : "l"(a.v));
}
__device__ __forceinline__ F2 bc(float s) { return pk(s, s); }
__device__ __forceinline__ F2 fadd2(F2 a, F2 b) {
    F2 r; asm("add.rn.f32x2 %0, %1, %2;" : "=l"(r.v) : "l"(a.v), "l"(b.v)); return r;
}
__device__ __forceinline__ F2 fmul2(F2 a, F2 b) {
    F2 r; asm("mul.rn.f32x2 %0, %1, %2;" : "=l"(r.v) : "l"(a.v), "l"(b.v)); return r;
}
__device__ __forceinline__ F2 ffma2(F2 a, F2 b, F2 c) {
    F2 r; asm("fma.rn.f32x2 %0, %1, %2, %3;" : "=l"(r.v) : "l"(a.v), "l"(b.v), "l"(c.v)); return r;
}

__device__ __forceinline__ float rcp_a(float x) {
    float r; asm("rcp.approx.f32 %0, %1;" : "=f"(r) : "f"(x)); return r;
}
__device__ __forceinline__ float rsq_a(float x) {
    float r; asm("rsqrt.approx.f32 %0, %1;" : "=f"(r) : "f"(x)); return r;
}
__device__ __forceinline__ float sqrt_a(float x) {
    float r; asm("sqrt.approx.f32 %0, %1;" : "=f"(r) : "f"(x)); return r;
}
__device__ __forceinline__ float ex2_a(float x) {
    float r; asm("ex2.approx.f32 %0, %1;" : "=f"(r) : "f"(x)); return r;
}
__device__ __forceinline__ F2 frcp2(F2 a) {
    float lo, hi; upk(a, lo, hi); return pk(rcp_a(lo), rcp_a(hi));
}
#define EXPA(x) ex2_a(1.4426950408889634f * (x))

// ---------------- main kernel: 1 pixel per thread, f32x2 across wavelengths ----------------
__global__ __launch_bounds__(32)
void pe_kernel(const float* __restrict__ X,     // (B,5,5)
               const float* __restrict__ Yg,    // (B,5)
               const float* __restrict__ ch0g,  // (B,1,3)
               const float* __restrict__ pf,    // (14,)
               const float* __restrict__ xag,   // (3,)
               const float* __restrict__ Sag,   // (3,3)
               const float* __restrict__ Seg,   // (5,5)
               const int*   __restrict__ nitp,
               float* __restrict__ out,         // (B,9)
               int B)
{
    int b = blockIdx.x * blockDim.x + threadIdx.x;
    if (b >= B) return;

    const float L[5] = {-0.275f, 0.025f, 0.5f, 0.70f, 1.15f};

    // ---- uniform (broadcast) parameters ----
    float p0=pf[0], p1=pf[1], p2=pf[2], p3=pf[3], p4=pf[4], p5=pf[5], p6=pf[6],
          p7=pf[7], p8=pf[8], p9=pf[9], p10=pf[10], p11=pf[11], p12=pf[12], p13=pf[13];

    float AphS[5], AcdS[5], BbsS[5];
    #pragma unroll
    for (int l = 0; l < 5; l++) {
        AphS[l] = p0 * 0.05f * (1.0f + p1 * 0.1f * L[l] + p2 * 0.01f);
        AcdS[l] = p5 * 0.1f * expf(-p6 * 1.7f * L[l]);
        BbsS[l] = p3 * 0.001f * (1.0f + p4 * 0.05f * L[l]);
    }
    const float cna = p12 * 0.005f;
    const float cnb = p13 * 0.005f;
    const float c7s = p7 * 0.089f;
    const float c8s = p8 * 0.1245f;

    // symmetrized matrices (uniform)
    float Se[5][5];
    #pragma unroll
    for (int i = 0; i < 5; i++)
        #pragma unroll
        for (int j = 0; j < 5; j++)
            Se[i][j] = 0.5f * (Seg[i*5 + j] + Seg[j*5 + i]);
    float SaS[3][3];
    #pragma unroll
    for (int i = 0; i < 3; i++)
        #pragma unroll
        for (int j = 0; j < 3; j++)
            SaS[i][j] = 0.5f * (Sag[i*3 + j] + Sag[j*3 + i]);
    float xa0 = xag[0], xa1 = xag[1], xa2 = xag[2];

    bool diag = (Se[0][1]==0.f && Se[0][2]==0.f && Se[0][3]==0.f && Se[0][4]==0.f &&
                 Se[1][2]==0.f && Se[1][3]==0.f && Se[1][4]==0.f &&
                 Se[2][3]==0.f && Se[2][4]==0.f && Se[3][4]==0.f &&
                 SaS[0][1]==0.f && SaS[0][2]==0.f && SaS[1][2]==0.f);

    // ---- per-pixel setup ----
    float fe[5], yv[5];
    #pragma unroll
    for (int l = 0; l < 5; l++) {
        float e0 = X[b*25 + l*5 + 0], e1 = X[b*25 + l*5 + 1];
        fe[l] = __fdividef(e0 + 0.5f*e1, e0 + e1);
        yv[l] = Yg[b*5 + l];
    }

    float ch[3], m[3] = {0.f,0.f,0.f};
    float v[3] = {1e-30f, 1e-30f, 1e-30f};   // exact-effect-free floor
    ch[0] = ch0g[b*3 + 0];
    ch[1] = ch0g[b*3 + 1];
    ch[2] = ch0g[b*3 + 2];

    int iters = 50;
    if (nitp) {
        int it = *nitp;
        if (it >= 1 && it <= 100000000) iters = it;
        else {
            float f = __int_as_float(it);
            if (f >= 1.0f && f <= 1e8f) iters = (int)f;
        }
    }

    float b1t = 1.0f, b2t = 1.0f;

    if (diag) {
        // ===== fused diagonal path: lambdas (0,1) and (2,3) packed, lambda 4 scalar =====
        // packed per-lambda-pair constants
        F2 ABSp[2], ABSn[2], ACDp[2], BBSp[2], FE2[2], YFN[2];
        #pragma unroll
        for (int i = 0; i < 2; i++) {
            int l0 = 2*i, l1 = 2*i + 1;
            float ab0 = AphS[l0] + BbsS[l0], ab1 = AphS[l1] + BbsS[l1];
            ABSp[i] = pk(ab0, ab1);
            ABSn[i] = pk(-ab0, -ab1);
            ACDp[i] = pk(AcdS[l0], AcdS[l1]);
            BBSp[i] = pk(BbsS[l0], BbsS[l1]);
            FE2[i]  = pk(Se[l0][l0]*fe[l0]*fe[l0], Se[l1][l1]*fe[l1]*fe[l1]);
            YFN[i]  = pk(-__fdividef(yv[l0], fe[l0]), -__fdividef(yv[l1], fe[l1]));
        }
        // scalar lambda-4 constants
        const float ab4 = AphS[4] + BbsS[4];
        const float acd4 = AcdS[4], bbs4 = BbsS[4];
        const float fe24 = Se[4][4]*fe[4]*fe[4];
        const float yfn4 = -__fdividef(yv[4], fe[4]);

        const float sa0 = SaS[0][0], sa1 = SaS[1][1], sa2 = SaS[2][2];
        const float bp0 = -sa0*xa0, bp1 = -sa1*xa1, bp2 = -sa2*xa2;
        const float cnab = cna + cnb;
        const F2 C7p = bc(c7s), C8p = bc(c8s);

        // tracked exponentials (scalar)
        float ex0 = EXPA(ch[0]);   // chla
        float ex1 = EXPA(ch[1]);   // nap
        float ex2v = EXPA(ch[2]);  // cdom

        for (int t = 0; t < iters; t++) {
            float chla = ex0, nap = ex1, cdom = ex2v;

            float dbb1  = cnb * nap;
            float dsum1 = cnab * nap;
            float NCs   = dsum1 + 0.0057f;
            float DB1Cs = dbb1 + 0.0012f;

            F2 CHLA2 = bc(chla), CDOM2 = bc(cdom);
            F2 NC2 = bc(NCs), DB1C2 = bc(DB1Cs);

            F2 acc0p = bc(0.0f), S0p = bc(0.0f), S1p = bc(0.0f), acc2p = bc(0.0f);

            #pragma unroll
            for (int i = 0; i < 2; i++) {
                F2 s  = ffma2(ABSp[i], CHLA2, ffma2(ACDp[i], CDOM2, NC2)); // a+bb
                F2 bb = ffma2(BBSp[i], CHLA2, DB1C2);
                F2 iv = frcp2(s);
                F2 u  = fmul2(bb, iv);
                F2 t1 = ffma2(C8p, u, C7p);
                F2 p  = ffma2(t1, u, YFN[i]);        // rrs/FE - Y/FE
                F2 d  = ffma2(C8p, u, t1);           // c7 + 2 c8 u
                F2 q  = fmul2(fmul2(FE2[i], iv), fmul2(p, d));
                F2 qu = fmul2(q, u);
                F2 tg = ffma2(u, ABSn[i], BBSp[i]);  // BBS - u*(Aph+Bbs)
                acc0p = ffma2(q, tg, acc0p);
                S0p   = fadd2(S0p, q);
                S1p   = fadd2(S1p, qu);
                acc2p = ffma2(qu, ACDp[i], acc2p);
            }

            // scalar lambda 4
            float s4  = fmaf(ab4, chla, fmaf(acd4, cdom, NCs));
            float bb4 = fmaf(bbs4, chla, DB1Cs);
            float iv4 = rcp_a(s4);
            float u4  = bb4 * iv4;
            float t14 = fmaf(c8s, u4, c7s);
            float p4v = fmaf(t14, u4, yfn4);
            float d4  = fmaf(c8s, u4, t14);
            float q4  = (fe24 * iv4) * (p4v * d4);
            float qu4 = q4 * u4;
            float tg4 = fmaf(-u4, ab4, bbs4);

            // lane reduction
            float a0l, a0h, s0l, s0h, s1l, s1h, a2l, a2h;
            upk(acc0p, a0l, a0h); upk(S0p, s0l, s0h);
            upk(S1p, s1l, s1h);   upk(acc2p, a2l, a2h);
            float acc0 = fmaf(q4, tg4, a0l + a0h);
            float S0   = (s0l + s0h) + q4;
            float S1   = (s1l + s1h) + qu4;
            float acc2 = fmaf(qu4, acd4, a2l + a2h);   // +sum qu*ACD

            // gradients
            float g0 = fmaf(acc0, chla, fmaf(sa0, ch[0], bp0));
            float g1 = fmaf(dbb1, S0, fmaf(sa1, ch[1], bp1)) - dsum1 * S1;
            float g2 = fmaf(-acc2, cdom, fmaf(sa2, ch[2], bp2));

            // scalar step size with exact bias correction
            b1t *= ADAM_B1; b2t *= ADAM_B2;
            float nlrt = -ADAM_LR * sqrt_a(1.0f - b2t) * rcp_a(1.0f - b1t);

            float g[3] = { g0, g1, g2 };
            float* exs[3] = { &ex0, &ex1, &ex2v };
            #pragma unroll
            for (int k = 0; k < 3; k++) {
                m[k] = fmaf(g[k], 1.0f - ADAM_B1, m[k] * ADAM_B1);
                v[k] = fmaf(g[k] * g[k], 1.0f - ADAM_B2, v[k] * ADAM_B2);
                float dlt = nlrt * m[k] * rsq_a(v[k]);
                ch[k] += dlt;
                // e^dlt via degree-3 poly (|dlt| <= ~0.06)
                float h = fmaf(dlt, 1.0f/6.0f, 0.5f);
                h = fmaf(dlt, h, 1.0f);
                h = fmaf(dlt, h, 1.0f);
                *exs[k] *= h;
            }
        }
    } else {
        // ===== general scalar two-pass fallback (dense Se, Sa) =====
        float bp0 = -(SaS[0][0]*xa0 + SaS[0][1]*xa1 + SaS[0][2]*xa2);
        float bp1 = -(SaS[1][0]*xa0 + SaS[1][1]*xa1 + SaS[1][2]*xa2);
        float bp2 = -(SaS[2][0]*xa0 + SaS[2][1]*xa1 + SaS[2][2]*xa2);

        for (int t = 0; t < iters; t++) {
            float chla = EXPA(ch[0]);
            float nap  = EXPA(ch[1]);
            float cdom = EXPA(ch[2]);

            float da1  = cna * nap;
            float dbb1 = cnb * nap;

            float r[5], u[5], iv[5];
            #pragma unroll
            for (int l = 0; l < 5; l++) {
                float a  = 0.0045f + AphS[l]*chla + AcdS[l]*cdom + da1;
                float bb = 0.0012f + BbsS[l]*chla + dbb1;
                iv[l] = rcp_a(a + bb);
                u[l]  = bb * iv[l];
                float rrs = fmaf(c8s, u[l], c7s) * u[l] * fe[l];
                r[l] = rrs - yv[l];
            }

            float g0 = fmaf(SaS[0][0], ch[0], fmaf(SaS[0][1], ch[1], fmaf(SaS[0][2], ch[2], bp0)));
            float g1 = fmaf(SaS[1][0], ch[0], fmaf(SaS[1][1], ch[1], fmaf(SaS[1][2], ch[2], bp1)));
            float g2 = fmaf(SaS[2][0], ch[0], fmaf(SaS[2][1], ch[1], fmaf(SaS[2][2], ch[2], bp2)));

            #pragma unroll
            for (int l = 0; l < 5; l++) {
                float w = fmaf(Se[l][0], r[0], fmaf(Se[l][1], r[1],
                          fmaf(Se[l][2], r[2], fmaf(Se[l][3], r[3], Se[l][4]*r[4]))));
                float dg = fmaf(2.0f*c8s, u[l], c7s) * fe[l];
                float q  = w * dg * iv[l];
                float ul = u[l], om = 1.0f - ul;
                float da0 = AphS[l]*chla, dbb0 = BbsS[l]*chla;
                float da2 = AcdS[l]*cdom;
                g0 += q * (om * dbb0 - ul * da0);
                g1 += q * (om * dbb1 - ul * da1);
                g2 -= q * ul * da2;
            }

            b1t *= ADAM_B1; b2t *= ADAM_B2;
            float nlrt = -ADAM_LR * sqrt_a(1.0f - b2t) * rcp_a(1.0f - b1t);
            float g[3] = { g0, g1, g2 };
            #pragma unroll
            for (int k = 0; k < 3; k++) {
                m[k] = fmaf(g[k], 1.0f - ADAM_B1, m[k] * ADAM_B1);
                v[k] = fmaf(g[k] * g[k], 1.0f - ADAM_B2, v[k] * ADAM_B2);
                ch[k] += nlrt * m[k] * rsq_a(v[k]);
            }
        }
    }

    // ---- outputs: [ch0, kd(5), bbp(3)] ----
    float kfac = p9 * 0.9f + p10 * 0.1f;
    float chla = EXPA(ch[0]);
    float nap  = EXPA(ch[1]);
    float cdom = EXPA(ch[2]);

    out[b*9 + 0] = ch[0];
    #pragma unroll
    for (int l = 0; l < 5; l++) {
        float a  = 0.0045f + AphS[l]*chla + AcdS[l]*cdom + cna*nap;
        float bb = 0.0012f + BbsS[l]*chla + cnb*nap;
        float x3 = X[b*25 + l*5 + 3];
        float mu = 0.5f + 0.5f * rcp_a(1.0f + EXPA(-x3));
        out[b*9 + 1 + l] = (a + bb) * rcp_a(mu) * kfac;
    }
    const float L3[3] = {0.025f, 0.5f, 1.15f};
    #pragma unroll
    for (int j = 0; j < 3; j++) {
        out[b*9 + 6 + j] = p11 * (p3 * 0.001f * chla * (1.0f + p4 * 0.05f * L3[j]) + cnb * nap);
    }
}

extern "C" void kernel_launch(void* const* d_in, const int* in_sizes, int n_in,
                              void* d_out, int out_size) {
    const float* X    = (const float*)d_in[0];
    const float* Y    = (const float*)d_in[1];
    const float* ch0  = (const float*)d_in[2];
    const float* pf   = (const float*)d_in[3];
    const float* xa   = (const float*)d_in[4];
    const float* Sa   = (const float*)d_in[5];
    const float* Se   = (const float*)d_in[6];
    const int*   nit  = (n_in >= 8) ? (const int*)d_in[7] : nullptr;
    float* out = (float*)d_out;

    int B = in_sizes[1] / 5;   // Y is (B,5)

    const int TPB = 32;
    int blocks = (B + TPB - 1) / TPB;
    pe_kernel<<<blocks, TPB>>>(X, Y, ch0, pf, xa, Sa, Se, nit, out, B);
}